// round 7
// baseline (speedup 1.0000x reference)
#include <cuda_runtime.h>
#include <cstdint>

#define Nn 50000
#define Ee 800000
#define Fd 128          // feature dim = H*OUT = 128
#define NH 2            // heads

// ---------------- scratch (no allocations allowed) ----------------
__device__ float g_f[(size_t)Nn * Fd];    // projected feats for current relation
__device__ float g_agg[(size_t)Nn * Fd];  // unnormalized aggregation
__device__ float g_h1[(size_t)Nn * Fd];   // layer-1 output
__device__ float g_el[(size_t)Nn * NH];
__device__ float g_er[(size_t)Nn * NH];
__device__ float g_s[(size_t)Nn * NH];    // softmax denominators

// ---------------- packed f32x2 helpers (Blackwell FFMA2 path) ----------------
__device__ __forceinline__ unsigned long long pack2(float lo, float hi) {
    unsigned long long r;
    asm("mov.b64 %0, {%1, %2};" : "=l"(r) : "f"(lo), "f"(hi));
    return r;
}
__device__ __forceinline__ void fma2(unsigned long long& d, unsigned long long a,
                                     unsigned long long b) {
    asm("fma.rn.f32x2 %0, %1, %2, %0;" : "+l"(d) : "l"(a), "l"(b));
}
__device__ __forceinline__ float2 unpack2(unsigned long long v) {
    float2 r;
    asm("mov.b64 {%0, %1}, %2;" : "=f"(r.x), "=f"(r.y) : "l"(v));
    return r;
}

// ---------------- GEMM: C[nrows,128] = A[nrows,128] @ B[128,128] ----------------
// 128x128 tile per block, 256 threads, thread tile 8 rows x (4 + 4 split) cols,
// accumulation in packed f32x2.
#define GEMM_SMEM (128 * 132 * 4 + 128 * 128 * 4)

__global__ void __launch_bounds__(256) gemm_k(const float* __restrict__ A,
                                              const float* __restrict__ B,
                                              float* __restrict__ C, int nrows) {
    extern __shared__ float sm[];
    float* As = sm;               // [128][132] padded
    float* Bs = sm + 128 * 132;   // [128][128]
    const int m0 = blockIdx.x * 128;
    const int tid = threadIdx.x;

#pragma unroll
    for (int it = 0; it < 16; it++) {
        int idx = tid + it * 256;       // float4 index, 0..4095
        int row = idx >> 5;
        int c4 = (idx & 31) << 2;
        float4 va = make_float4(0.f, 0.f, 0.f, 0.f);
        if (m0 + row < nrows) va = *(const float4*)&A[(size_t)(m0 + row) * Fd + c4];
        *(float4*)&As[row * 132 + c4] = va;
        *(float4*)&Bs[row * 128 + c4] = *(const float4*)&B[row * Fd + c4];
    }
    __syncthreads();

    const int ty = tid >> 4;   // 0..15 -> rows ty*8..ty*8+7
    const int tx = tid & 15;   // cols tx*4..tx*4+3 and 64+tx*4..64+tx*4+3

    unsigned long long acc[8][4];
#pragma unroll
    for (int i = 0; i < 8; i++)
#pragma unroll
        for (int j = 0; j < 4; j++) acc[i][j] = 0ull;

#pragma unroll 4
    for (int k = 0; k < 128; k++) {
        float4 b0 = *(const float4*)&Bs[k * 128 + tx * 4];
        float4 b1 = *(const float4*)&Bs[k * 128 + 64 + tx * 4];
        unsigned long long bp0 = pack2(b0.x, b0.y);
        unsigned long long bp1 = pack2(b0.z, b0.w);
        unsigned long long bp2 = pack2(b1.x, b1.y);
        unsigned long long bp3 = pack2(b1.z, b1.w);
#pragma unroll
        for (int i = 0; i < 8; i++) {
            float a = As[(ty * 8 + i) * 132 + k];
            unsigned long long ap = pack2(a, a);
            fma2(acc[i][0], ap, bp0);
            fma2(acc[i][1], ap, bp1);
            fma2(acc[i][2], ap, bp2);
            fma2(acc[i][3], ap, bp3);
        }
    }

#pragma unroll
    for (int i = 0; i < 8; i++) {
        int row = m0 + ty * 8 + i;
        if (row < nrows) {
            float2 v0 = unpack2(acc[i][0]);
            float2 v1 = unpack2(acc[i][1]);
            float2 v2 = unpack2(acc[i][2]);
            float2 v3 = unpack2(acc[i][3]);
            *(float4*)&C[(size_t)row * Fd + tx * 4] = make_float4(v0.x, v0.y, v1.x, v1.y);
            *(float4*)&C[(size_t)row * Fd + 64 + tx * 4] = make_float4(v2.x, v2.y, v3.x, v3.y);
        }
    }
}

// ---------------- per-node attention scores: el/er[n,h] = dot(f[n,h,:], al/ar[h,:]) ----------------
__global__ void __launch_bounds__(256) scores_k(const float* __restrict__ f,
                                                const float* __restrict__ al,
                                                const float* __restrict__ ar,
                                                float* __restrict__ el,
                                                float* __restrict__ er) {
    int w = (int)(((size_t)blockIdx.x * blockDim.x + threadIdx.x) >> 5);
    if (w >= Nn) return;
    int lane = threadIdx.x & 31;
    float4 fv = *(const float4*)&f[(size_t)w * Fd + lane * 4];
    float4 av = *(const float4*)&al[lane * 4];
    float4 rv = *(const float4*)&ar[lane * 4];
    float pel = fv.x * av.x + fv.y * av.y + fv.z * av.z + fv.w * av.w;
    float per = fv.x * rv.x + fv.y * rv.y + fv.z * rv.z + fv.w * rv.w;
#pragma unroll
    for (int off = 8; off; off >>= 1) {
        pel += __shfl_down_sync(0xffffffffu, pel, off, 16);
        per += __shfl_down_sync(0xffffffffu, per, off, 16);
    }
    if ((lane & 15) == 0) {
        int h = lane >> 4;
        el[w * NH + h] = pel;
        er[w * NH + h] = per;
    }
}

// ---------------- edge pass: one warp per edge ----------------
// Softmax shift-invariance => skip segment-max (scores are O(1), no overflow).
// Normalization factors out => accumulate unnormalized: agg[dst] += f[src]*exp(e),
// s[dst] += exp(e). Vector RED (no return) for the 128-float scatter.
__global__ void __launch_bounds__(256) edge_k(const int* __restrict__ src,
                                              const int* __restrict__ dst,
                                              const float* __restrict__ el,
                                              const float* __restrict__ er,
                                              const float* __restrict__ f,
                                              float* __restrict__ agg,
                                              float* __restrict__ s) {
    long long gw = ((long long)blockIdx.x * blockDim.x + threadIdx.x) >> 5;
    if (gw >= Ee) return;
    int lane = threadIdx.x & 31;
    int u = __ldg(&src[gw]);
    int v = __ldg(&dst[gw]);
    int h = lane >> 4;
    float e = __ldg(&el[u * NH + h]) + __ldg(&er[v * NH + h]);
    e = (e > 0.f) ? e : 0.2f * e;           // leaky_relu(0.2)
    float w = __expf(e);
    if ((lane & 15) == 0) atomicAdd(&s[v * NH + h], w);
    float4 fv = *(const float4*)&f[(size_t)u * Fd + lane * 4];
    float* p = &agg[(size_t)v * Fd + lane * 4];
    asm volatile("red.global.add.v4.f32 [%0], {%1, %2, %3, %4};" ::"l"(p),
                 "f"(fv.x * w), "f"(fv.y * w), "f"(fv.z * w), "f"(fv.w * w)
                 : "memory");
}

// ---------------- epilogue: hout += elu(agg/s + b) ----------------
__global__ void __launch_bounds__(256) epi_k(const float* __restrict__ agg,
                                             const float* __restrict__ s,
                                             const float* __restrict__ b,
                                             float* __restrict__ hout) {
    int i = blockIdx.x * blockDim.x + threadIdx.x;
    if (i >= Nn * Fd) return;
    int n = i >> 7;
    int c = i & 127;
    int h = c >> 6;
    float sv = s[n * NH + h];
    float v = (sv > 0.f) ? agg[i] / sv : 0.f;  // nodes w/o in-edges: agg term is 0
    v += b[c];
    hout[i] += (v > 0.f) ? v : expm1f(v);      // elu, alpha=1
}

// ---------------- layer driver ----------------
static void run_layer(const float* hin, const float* W, const float* al,
                      const float* ar, const float* b, const int* src,
                      const int* dst, float* hout, float* f, float* agg,
                      float* el, float* er, float* s) {
    cudaMemsetAsync(hout, 0, (size_t)Nn * Fd * sizeof(float));
    for (int r = 0; r < 2; r++) {
        gemm_k<<<(Nn + 127) / 128, 256, GEMM_SMEM>>>(hin, W + (size_t)r * Fd * Fd, f, Nn);
        scores_k<<<(Nn * 32 + 255) / 256, 256>>>(f, al + r * Fd, ar + r * Fd, el, er);
        cudaMemsetAsync(agg, 0, (size_t)Nn * Fd * sizeof(float));
        cudaMemsetAsync(s, 0, (size_t)Nn * NH * sizeof(float));
        edge_k<<<(int)(((long long)Ee * 32) / 256), 256>>>(
            src + (size_t)r * Ee, dst + (size_t)r * Ee, el, er, f, agg, s);
        epi_k<<<(Nn * Fd + 255) / 256, 256>>>(agg, s, b + r * Fd, hout);
    }
}

extern "C" void kernel_launch(void* const* d_in, const int* in_sizes, int n_in,
                              void* d_out, int out_size) {
    const float* x   = (const float*)d_in[0];
    const float* W0  = (const float*)d_in[1];
    const float* al0 = (const float*)d_in[2];
    const float* ar0 = (const float*)d_in[3];
    const float* b0  = (const float*)d_in[4];
    const float* W1  = (const float*)d_in[5];
    const float* al1 = (const float*)d_in[6];
    const float* ar1 = (const float*)d_in[7];
    const float* b1  = (const float*)d_in[8];
    const int* src0  = (const int*)d_in[9];
    const int* dst0  = (const int*)d_in[10];
    const int* src1  = (const int*)d_in[11];
    const int* dst1  = (const int*)d_in[12];
    float* out = (float*)d_out;

    float *f, *agg, *h1, *el, *er, *s;
    cudaGetSymbolAddress((void**)&f, g_f);
    cudaGetSymbolAddress((void**)&agg, g_agg);
    cudaGetSymbolAddress((void**)&h1, g_h1);
    cudaGetSymbolAddress((void**)&el, g_el);
    cudaGetSymbolAddress((void**)&er, g_er);
    cudaGetSymbolAddress((void**)&s, g_s);

    cudaFuncSetAttribute(gemm_k, cudaFuncAttributeMaxDynamicSharedMemorySize,
                         GEMM_SMEM);

    run_layer(x, W0, al0, ar0, b0, src0, dst0, h1, f, agg, el, er, s);
    run_layer(h1, W1, al1, ar1, b1, src1, dst1, out, f, agg, el, er, s);
}

// round 8
// speedup vs baseline: 1.7299x; 1.7299x over previous
#include <cuda_runtime.h>
#include <cstdint>

#define Nn 50000
#define Ee 800000
#define Fd 128          // feature dim = H*OUT = 128
#define NH 2            // heads

// ---------------- scratch (no allocations allowed) ----------------
__device__ float g_f0[(size_t)Nn * Fd];   // projected feats, relation 0
__device__ float g_f1[(size_t)Nn * Fd];   // projected feats, relation 1
__device__ float g_h1[(size_t)Nn * Fd];   // layer-1 output
__device__ float g_el0[(size_t)Nn * NH];
__device__ float g_er0[(size_t)Nn * NH];
__device__ float g_el1[(size_t)Nn * NH];
__device__ float g_er1[(size_t)Nn * NH];
__device__ int   g_ptr[4][Nn];            // per-graph rowptr (hist -> scan -> scatter)
__device__ int   g_csr[4][Ee];            // per-graph src ids grouped by dst
__device__ int   g_part[64];              // scan block partials

// ---------------- packed f32x2 helpers (Blackwell FFMA2 path) ----------------
__device__ __forceinline__ unsigned long long pack2(float lo, float hi) {
    unsigned long long r;
    asm("mov.b64 %0, {%1, %2};" : "=l"(r) : "f"(lo), "f"(hi));
    return r;
}
__device__ __forceinline__ void fma2(unsigned long long& d, unsigned long long a,
                                     unsigned long long b) {
    asm("fma.rn.f32x2 %0, %1, %2, %0;" : "+l"(d) : "l"(a), "l"(b));
}
__device__ __forceinline__ float2 unpack2(unsigned long long v) {
    float2 r;
    asm("mov.b64 {%0, %1}, %2;" : "=f"(r.x), "=f"(r.y) : "l"(v));
    return r;
}

// ---------------- GEMM: C[nrows,128] = A[nrows,128] @ B[128,128] ----------------
#define GEMM_SMEM (128 * 132 * 4 + 128 * 128 * 4)

__global__ void __launch_bounds__(256) gemm_k(const float* __restrict__ A,
                                              const float* __restrict__ B,
                                              float* __restrict__ C, int nrows) {
    extern __shared__ float sm[];
    float* As = sm;               // [128][132] padded
    float* Bs = sm + 128 * 132;   // [128][128]
    const int m0 = blockIdx.x * 128;
    const int tid = threadIdx.x;

#pragma unroll
    for (int it = 0; it < 16; it++) {
        int idx = tid + it * 256;       // float4 index, 0..4095
        int row = idx >> 5;
        int c4 = (idx & 31) << 2;
        float4 va = make_float4(0.f, 0.f, 0.f, 0.f);
        if (m0 + row < nrows) va = *(const float4*)&A[(size_t)(m0 + row) * Fd + c4];
        *(float4*)&As[row * 132 + c4] = va;
        *(float4*)&Bs[row * 128 + c4] = *(const float4*)&B[row * Fd + c4];
    }
    __syncthreads();

    const int ty = tid >> 4;   // rows ty*8..ty*8+7
    const int tx = tid & 15;   // cols tx*4..+3 and 64+tx*4..+3

    unsigned long long acc[8][4];
#pragma unroll
    for (int i = 0; i < 8; i++)
#pragma unroll
        for (int j = 0; j < 4; j++) acc[i][j] = 0ull;

#pragma unroll 4
    for (int k = 0; k < 128; k++) {
        float4 b0 = *(const float4*)&Bs[k * 128 + tx * 4];
        float4 b1 = *(const float4*)&Bs[k * 128 + 64 + tx * 4];
        unsigned long long bp0 = pack2(b0.x, b0.y);
        unsigned long long bp1 = pack2(b0.z, b0.w);
        unsigned long long bp2 = pack2(b1.x, b1.y);
        unsigned long long bp3 = pack2(b1.z, b1.w);
#pragma unroll
        for (int i = 0; i < 8; i++) {
            float a = As[(ty * 8 + i) * 132 + k];
            unsigned long long ap = pack2(a, a);
            fma2(acc[i][0], ap, bp0);
            fma2(acc[i][1], ap, bp1);
            fma2(acc[i][2], ap, bp2);
            fma2(acc[i][3], ap, bp3);
        }
    }

#pragma unroll
    for (int i = 0; i < 8; i++) {
        int row = m0 + ty * 8 + i;
        if (row < nrows) {
            float2 v0 = unpack2(acc[i][0]);
            float2 v1 = unpack2(acc[i][1]);
            float2 v2 = unpack2(acc[i][2]);
            float2 v3 = unpack2(acc[i][3]);
            *(float4*)&C[(size_t)row * Fd + tx * 4] = make_float4(v0.x, v0.y, v1.x, v1.y);
            *(float4*)&C[(size_t)row * Fd + 64 + tx * 4] = make_float4(v2.x, v2.y, v3.x, v3.y);
        }
    }
}

// ---------------- per-node attention scores ----------------
__global__ void __launch_bounds__(256) scores_k(const float* __restrict__ f,
                                                const float* __restrict__ al,
                                                const float* __restrict__ ar,
                                                float* __restrict__ el,
                                                float* __restrict__ er) {
    int w = (int)(((size_t)blockIdx.x * blockDim.x + threadIdx.x) >> 5);
    if (w >= Nn) return;
    int lane = threadIdx.x & 31;
    float4 fv = *(const float4*)&f[(size_t)w * Fd + lane * 4];
    float4 av = *(const float4*)&al[lane * 4];
    float4 rv = *(const float4*)&ar[lane * 4];
    float pel = fv.x * av.x + fv.y * av.y + fv.z * av.z + fv.w * av.w;
    float per = fv.x * rv.x + fv.y * rv.y + fv.z * rv.z + fv.w * rv.w;
#pragma unroll
    for (int off = 8; off; off >>= 1) {
        pel += __shfl_down_sync(0xffffffffu, pel, off, 16);
        per += __shfl_down_sync(0xffffffffu, per, off, 16);
    }
    if ((lane & 15) == 0) {
        int h = lane >> 4;
        el[w * NH + h] = pel;
        er[w * NH + h] = per;
    }
}

// ---------------- CSR build: hist -> 3-phase scan -> scatter ----------------
__global__ void __launch_bounds__(256) hist_k(const int* __restrict__ dst,
                                              int* __restrict__ cnt) {
    int e = blockIdx.x * blockDim.x + threadIdx.x;
    if (e >= Ee) return;
    atomicAdd(&cnt[dst[e]], 1);
}

__global__ void __launch_bounds__(1024) scanA_k(int* __restrict__ cnt,
                                                int* __restrict__ part) {
    __shared__ int sm[1024];
    int i = blockIdx.x * 1024 + threadIdx.x;
    int v = (i < Nn) ? cnt[i] : 0;
    sm[threadIdx.x] = v;
    __syncthreads();
#pragma unroll
    for (int off = 1; off < 1024; off <<= 1) {
        int t = (threadIdx.x >= off) ? sm[threadIdx.x - off] : 0;
        __syncthreads();
        sm[threadIdx.x] += t;
        __syncthreads();
    }
    int incl = sm[threadIdx.x];
    if (i < Nn) cnt[i] = incl - v;               // exclusive within block
    if (threadIdx.x == 1023) part[blockIdx.x] = incl;
}

__global__ void scanB_k(int* __restrict__ part, int nb) {
    if (threadIdx.x == 0) {
        int acc = 0;
        for (int i = 0; i < nb; i++) { int t = part[i]; part[i] = acc; acc += t; }
    }
}

__global__ void __launch_bounds__(1024) scanC_k(int* __restrict__ cnt,
                                                const int* __restrict__ part) {
    int i = blockIdx.x * 1024 + threadIdx.x;
    if (i < Nn) cnt[i] += part[blockIdx.x];
}

// scatter: ptr[v] holds exclusive start; atomic bump converts it to the
// inclusive end, so gather reads [ptr[v-1], ptr[v]).
__global__ void __launch_bounds__(256) scat_k(const int* __restrict__ src,
                                              const int* __restrict__ dst,
                                              int* __restrict__ ptr,
                                              int* __restrict__ csr) {
    int e = blockIdx.x * blockDim.x + threadIdx.x;
    if (e >= Ee) return;
    int v = dst[e];
    int pos = atomicAdd(&ptr[v], 1);
    csr[pos] = src[e];
}

// ---------------- fused gather + softmax-normalize + elu, both relations ------
__device__ __forceinline__ float eluf(float v) {
    return (v > 0.f) ? v : expm1f(v);
}

__global__ void __launch_bounds__(256) gather_k(
    const int* __restrict__ p0, const int* __restrict__ c0,
    const float* __restrict__ f0, const float* __restrict__ el0,
    const float* __restrict__ er0, const float* __restrict__ bb0,
    const int* __restrict__ p1, const int* __restrict__ c1,
    const float* __restrict__ f1, const float* __restrict__ el1,
    const float* __restrict__ er1, const float* __restrict__ bb1,
    float* __restrict__ hout) {
    int v = (int)(((size_t)blockIdx.x * blockDim.x + threadIdx.x) >> 5);
    if (v >= Nn) return;
    int lane = threadIdx.x & 31;
    int h = lane >> 4;  // lanes 0-15: head 0 (cols 0-63), 16-31: head 1

    float ox, oy, oz, ow;
    // relation 0
    {
        int beg = v ? __ldg(&p0[v - 1]) : 0;
        int end = __ldg(&p0[v]);
        float erh = __ldg(&er0[v * NH + h]);
        float ax = 0.f, ay = 0.f, az = 0.f, aw = 0.f, s = 0.f;
        for (int e = beg; e < end; e++) {
            int u = __ldg(&c0[e]);
            float sc = __ldg(&el0[u * NH + h]) + erh;
            sc = (sc > 0.f) ? sc : 0.2f * sc;
            float w = __expf(sc);
            s += w;
            float4 fv = *(const float4*)&f0[(size_t)u * Fd + lane * 4];
            ax += fv.x * w; ay += fv.y * w; az += fv.z * w; aw += fv.w * w;
        }
        float inv = (s > 0.f) ? 1.f / s : 0.f;
        float4 bv = *(const float4*)&bb0[lane * 4];
        ox = eluf(ax * inv + bv.x);
        oy = eluf(ay * inv + bv.y);
        oz = eluf(az * inv + bv.z);
        ow = eluf(aw * inv + bv.w);
    }
    // relation 1
    {
        int beg = v ? __ldg(&p1[v - 1]) : 0;
        int end = __ldg(&p1[v]);
        float erh = __ldg(&er1[v * NH + h]);
        float ax = 0.f, ay = 0.f, az = 0.f, aw = 0.f, s = 0.f;
        for (int e = beg; e < end; e++) {
            int u = __ldg(&c1[e]);
            float sc = __ldg(&el1[u * NH + h]) + erh;
            sc = (sc > 0.f) ? sc : 0.2f * sc;
            float w = __expf(sc);
            s += w;
            float4 fv = *(const float4*)&f1[(size_t)u * Fd + lane * 4];
            ax += fv.x * w; ay += fv.y * w; az += fv.z * w; aw += fv.w * w;
        }
        float inv = (s > 0.f) ? 1.f / s : 0.f;
        float4 bv = *(const float4*)&bb1[lane * 4];
        ox += eluf(ax * inv + bv.x);
        oy += eluf(ay * inv + bv.y);
        oz += eluf(az * inv + bv.z);
        ow += eluf(aw * inv + bv.w);
    }
    *(float4*)&hout[(size_t)v * Fd + lane * 4] = make_float4(ox, oy, oz, ow);
}

// ---------------- drivers ----------------
static void build_csr(const int* src, const int* dst, int* ptr, int* csr, int* part) {
    const int NB = (Nn + 1023) / 1024;  // 49
    cudaMemsetAsync(ptr, 0, (size_t)Nn * sizeof(int));
    hist_k<<<(Ee + 255) / 256, 256>>>(dst, ptr);
    scanA_k<<<NB, 1024>>>(ptr, part);
    scanB_k<<<1, 32>>>(part, NB);
    scanC_k<<<NB, 1024>>>(ptr, part);
    scat_k<<<(Ee + 255) / 256, 256>>>(src, dst, ptr, csr);
}

static void run_layer(const float* hin, const float* W, const float* al,
                      const float* ar, const float* b,
                      const int* ptrA, const int* csrA,
                      const int* ptrB, const int* csrB,
                      float* f0, float* f1,
                      float* el0, float* er0, float* el1, float* er1,
                      float* hout) {
    gemm_k<<<(Nn + 127) / 128, 256, GEMM_SMEM>>>(hin, W, f0, Nn);
    gemm_k<<<(Nn + 127) / 128, 256, GEMM_SMEM>>>(hin, W + (size_t)Fd * Fd, f1, Nn);
    scores_k<<<(Nn * 32 + 255) / 256, 256>>>(f0, al, ar, el0, er0);
    scores_k<<<(Nn * 32 + 255) / 256, 256>>>(f1, al + Fd, ar + Fd, el1, er1);
    gather_k<<<(Nn * 32 + 255) / 256, 256>>>(ptrA, csrA, f0, el0, er0, b,
                                             ptrB, csrB, f1, el1, er1, b + Fd,
                                             hout);
}

extern "C" void kernel_launch(void* const* d_in, const int* in_sizes, int n_in,
                              void* d_out, int out_size) {
    const float* x   = (const float*)d_in[0];
    const float* W0  = (const float*)d_in[1];
    const float* al0 = (const float*)d_in[2];
    const float* ar0 = (const float*)d_in[3];
    const float* b0  = (const float*)d_in[4];
    const float* W1  = (const float*)d_in[5];
    const float* al1 = (const float*)d_in[6];
    const float* ar1 = (const float*)d_in[7];
    const float* b1  = (const float*)d_in[8];
    const int* src0  = (const int*)d_in[9];
    const int* dst0  = (const int*)d_in[10];
    const int* src1  = (const int*)d_in[11];
    const int* dst1  = (const int*)d_in[12];
    float* out = (float*)d_out;

    float *f0, *f1, *h1, *el0, *er0, *el1, *er1;
    int *ptr, *csr, *part;
    cudaGetSymbolAddress((void**)&f0, g_f0);
    cudaGetSymbolAddress((void**)&f1, g_f1);
    cudaGetSymbolAddress((void**)&h1, g_h1);
    cudaGetSymbolAddress((void**)&el0, g_el0);
    cudaGetSymbolAddress((void**)&er0, g_er0);
    cudaGetSymbolAddress((void**)&el1, g_el1);
    cudaGetSymbolAddress((void**)&er1, g_er1);
    cudaGetSymbolAddress((void**)&ptr, g_ptr);
    cudaGetSymbolAddress((void**)&csr, g_csr);
    cudaGetSymbolAddress((void**)&part, g_part);

    cudaFuncSetAttribute(gemm_k, cudaFuncAttributeMaxDynamicSharedMemorySize,
                         GEMM_SMEM);

    // 4 graphs: (layer0,r0), (layer0,r1), (layer1,r0), (layer1,r1)
    build_csr(src0,      dst0,      ptr + 0 * Nn, csr + (size_t)0 * Ee, part);
    build_csr(src0 + Ee, dst0 + Ee, ptr + 1 * Nn, csr + (size_t)1 * Ee, part);
    build_csr(src1,      dst1,      ptr + 2 * Nn, csr + (size_t)2 * Ee, part);
    build_csr(src1 + Ee, dst1 + Ee, ptr + 3 * Nn, csr + (size_t)3 * Ee, part);

    run_layer(x, W0, al0, ar0, b0,
              ptr + 0 * Nn, csr + (size_t)0 * Ee,
              ptr + 1 * Nn, csr + (size_t)1 * Ee,
              f0, f1, el0, er0, el1, er1, h1);
    run_layer(h1, W1, al1, ar1, b1,
              ptr + 2 * Nn, csr + (size_t)2 * Ee,
              ptr + 3 * Nn, csr + (size_t)3 * Ee,
              f0, f1, el0, er0, el1, er1, out);
}

// round 9
// speedup vs baseline: 2.1041x; 1.2163x over previous
#include <cuda_runtime.h>
#include <cuda_fp16.h>
#include <cstdint>

#define Nn 50000
#define Ee 800000
#define Fd 128          // feature dim = H*OUT = 128
#define NH 2            // heads
#define NB_SCAN 49      // ceil(Nn/1024)

// ---------------- scratch (no allocations allowed) ----------------
__device__ __half g_f0[(size_t)Nn * Fd];  // projected feats (fp16), relation 0
__device__ __half g_f1[(size_t)Nn * Fd];  // projected feats (fp16), relation 1
__device__ float  g_h1[(size_t)Nn * Fd];  // layer-1 output
__device__ float  g_el0[(size_t)Nn * NH];
__device__ float  g_er0[(size_t)Nn * NH];
__device__ float  g_el1[(size_t)Nn * NH];
__device__ float  g_er1[(size_t)Nn * NH];
__device__ int    g_ptr[4][Nn];           // per-graph rowptr
__device__ int    g_csr[4][Ee];           // per-graph src ids grouped by dst
__device__ int    g_part[4 * 64];         // scan block partials

// ---------------- packed f32x2 helpers (Blackwell FFMA2 path) ----------------
__device__ __forceinline__ unsigned long long pack2(float lo, float hi) {
    unsigned long long r;
    asm("mov.b64 %0, {%1, %2};" : "=l"(r) : "f"(lo), "f"(hi));
    return r;
}
__device__ __forceinline__ void fma2(unsigned long long& d, unsigned long long a,
                                     unsigned long long b) {
    asm("fma.rn.f32x2 %0, %1, %2, %0;" : "+l"(d) : "l"(a), "l"(b));
}
__device__ __forceinline__ float2 unpack2(unsigned long long v) {
    float2 r;
    asm("mov.b64 {%0, %1}, %2;" : "=f"(r.x), "=f"(r.y) : "l"(v));
    return r;
}

// ---------------- GEMM + fused scores: both relations in one launch ----------
// C[nrows,128] = A[nrows,128] @ W[r], stored fp16; el/er computed from fp32
// accumulators via width-16 shfl reductions. blockIdx.y = relation.
#define GEMM_SMEM (128 * 132 * 4 + 128 * 128 * 4)

__global__ void __launch_bounds__(256) gemm_scores_k(
    const float* __restrict__ A, const float* __restrict__ W,
    const float* __restrict__ al, const float* __restrict__ ar,
    __half* __restrict__ fo0, __half* __restrict__ fo1,
    float* __restrict__ el0, float* __restrict__ er0,
    float* __restrict__ el1, float* __restrict__ er1, int nrows) {
    extern __shared__ float sm[];
    float* As = sm;               // [128][132] padded
    float* Bs = sm + 128 * 132;   // [128][128]
    const int r = blockIdx.y;
    const float* B = W + (size_t)r * Fd * Fd;
    __half* fout = r ? fo1 : fo0;
    float* el = r ? el1 : el0;
    float* er = r ? er1 : er0;
    const float* alr = al + r * Fd;
    const float* arr = ar + r * Fd;
    const int m0 = blockIdx.x * 128;
    const int tid = threadIdx.x;

#pragma unroll
    for (int it = 0; it < 16; it++) {
        int idx = tid + it * 256;       // float4 index, 0..4095
        int row = idx >> 5;
        int c4 = (idx & 31) << 2;
        float4 va = make_float4(0.f, 0.f, 0.f, 0.f);
        if (m0 + row < nrows) va = *(const float4*)&A[(size_t)(m0 + row) * Fd + c4];
        *(float4*)&As[row * 132 + c4] = va;
        *(float4*)&Bs[row * 128 + c4] = *(const float4*)&B[row * Fd + c4];
    }
    __syncthreads();

    const int ty = tid >> 4;   // rows ty*8..ty*8+7
    const int tx = tid & 15;   // cols tx*4 (head0) and 64+tx*4 (head1)

    unsigned long long acc[8][4];
#pragma unroll
    for (int i = 0; i < 8; i++)
#pragma unroll
        for (int j = 0; j < 4; j++) acc[i][j] = 0ull;

#pragma unroll 4
    for (int k = 0; k < 128; k++) {
        float4 b0 = *(const float4*)&Bs[k * 128 + tx * 4];
        float4 b1 = *(const float4*)&Bs[k * 128 + 64 + tx * 4];
        unsigned long long bp0 = pack2(b0.x, b0.y);
        unsigned long long bp1 = pack2(b0.z, b0.w);
        unsigned long long bp2 = pack2(b1.x, b1.y);
        unsigned long long bp3 = pack2(b1.z, b1.w);
#pragma unroll
        for (int i = 0; i < 8; i++) {
            float a = As[(ty * 8 + i) * 132 + k];
            unsigned long long ap = pack2(a, a);
            fma2(acc[i][0], ap, bp0);
            fma2(acc[i][1], ap, bp1);
            fma2(acc[i][2], ap, bp2);
            fma2(acc[i][3], ap, bp3);
        }
    }

    float4 alv0 = __ldg((const float4*)&alr[tx * 4]);
    float4 alv1 = __ldg((const float4*)&alr[64 + tx * 4]);
    float4 arv0 = __ldg((const float4*)&arr[tx * 4]);
    float4 arv1 = __ldg((const float4*)&arr[64 + tx * 4]);

#pragma unroll
    for (int i = 0; i < 8; i++) {
        int row = m0 + ty * 8 + i;
        float2 v0 = unpack2(acc[i][0]);
        float2 v1 = unpack2(acc[i][1]);
        float2 v2 = unpack2(acc[i][2]);
        float2 v3 = unpack2(acc[i][3]);
        // scores partials (per head), fp32-exact
        float pel0 = v0.x * alv0.x + v0.y * alv0.y + v1.x * alv0.z + v1.y * alv0.w;
        float pel1 = v2.x * alv1.x + v2.y * alv1.y + v3.x * alv1.z + v3.y * alv1.w;
        float per0 = v0.x * arv0.x + v0.y * arv0.y + v1.x * arv0.z + v1.y * arv0.w;
        float per1 = v2.x * arv1.x + v2.y * arv1.y + v3.x * arv1.z + v3.y * arv1.w;
#pragma unroll
        for (int off = 8; off; off >>= 1) {
            pel0 += __shfl_down_sync(0xffffffffu, pel0, off, 16);
            pel1 += __shfl_down_sync(0xffffffffu, pel1, off, 16);
            per0 += __shfl_down_sync(0xffffffffu, per0, off, 16);
            per1 += __shfl_down_sync(0xffffffffu, per1, off, 16);
        }
        if (row < nrows) {
            __half2 ha = __floats2half2_rn(v0.x, v0.y);
            __half2 hb = __floats2half2_rn(v1.x, v1.y);
            __half2 hc = __floats2half2_rn(v2.x, v2.y);
            __half2 hd = __floats2half2_rn(v3.x, v3.y);
            uint2 s0, s1;
            s0.x = *(unsigned int*)&ha; s0.y = *(unsigned int*)&hb;
            s1.x = *(unsigned int*)&hc; s1.y = *(unsigned int*)&hd;
            *(uint2*)&fout[(size_t)row * Fd + tx * 4] = s0;
            *(uint2*)&fout[(size_t)row * Fd + 64 + tx * 4] = s1;
            if (tx == 0) {
                el[row * NH + 0] = pel0;
                el[row * NH + 1] = pel1;
                er[row * NH + 0] = per0;
                er[row * NH + 1] = per1;
            }
        }
    }
}

// ---------------- batched CSR build (4 graphs in one pass each) --------------
__global__ void __launch_bounds__(256) hist4_k(const int* __restrict__ dA,
                                               const int* __restrict__ dB,
                                               int* __restrict__ cnt) {
    long long e = (long long)blockIdx.x * blockDim.x + threadIdx.x;
    if (e >= 4LL * Ee) return;
    int g = (int)(e / Ee);
    int i = (int)(e - (long long)g * Ee);
    const int* d = (g < 2) ? (dA + (size_t)g * Ee) : (dB + (size_t)(g - 2) * Ee);
    atomicAdd(&cnt[g * Nn + d[i]], 1);
}

__global__ void __launch_bounds__(1024) scanA_k(int* __restrict__ cnt,
                                                int* __restrict__ part) {
    __shared__ int sm[1024];
    int g = blockIdx.y;
    int i = blockIdx.x * 1024 + threadIdx.x;
    int v = (i < Nn) ? cnt[g * Nn + i] : 0;
    sm[threadIdx.x] = v;
    __syncthreads();
#pragma unroll
    for (int off = 1; off < 1024; off <<= 1) {
        int t = (threadIdx.x >= off) ? sm[threadIdx.x - off] : 0;
        __syncthreads();
        sm[threadIdx.x] += t;
        __syncthreads();
    }
    int incl = sm[threadIdx.x];
    if (i < Nn) cnt[g * Nn + i] = incl - v;        // exclusive within block
    if (threadIdx.x == 1023) part[g * 64 + blockIdx.x] = incl;
}

__global__ void scanB_k(int* __restrict__ part) {
    if (threadIdx.x == 0) {
        int* p = part + blockIdx.x * 64;
        int acc = 0;
        for (int i = 0; i < NB_SCAN; i++) { int t = p[i]; p[i] = acc; acc += t; }
    }
}

__global__ void __launch_bounds__(1024) scanC_k(int* __restrict__ cnt,
                                                const int* __restrict__ part) {
    int g = blockIdx.y;
    int i = blockIdx.x * 1024 + threadIdx.x;
    if (i < Nn) cnt[g * Nn + i] += part[g * 64 + blockIdx.x];
}

// scatter: ptr[v] holds exclusive start; atomic bump -> inclusive end.
__global__ void __launch_bounds__(256) scat4_k(const int* __restrict__ sA,
                                               const int* __restrict__ dA,
                                               const int* __restrict__ sB,
                                               const int* __restrict__ dB,
                                               int* __restrict__ ptr,
                                               int* __restrict__ csr) {
    long long e = (long long)blockIdx.x * blockDim.x + threadIdx.x;
    if (e >= 4LL * Ee) return;
    int g = (int)(e / Ee);
    int i = (int)(e - (long long)g * Ee);
    const int* s = (g < 2) ? (sA + (size_t)g * Ee) : (sB + (size_t)(g - 2) * Ee);
    const int* d = (g < 2) ? (dA + (size_t)g * Ee) : (dB + (size_t)(g - 2) * Ee);
    int v = d[i];
    int pos = atomicAdd(&ptr[g * Nn + v], 1);
    csr[(size_t)g * Ee + pos] = s[i];
}

// ---------------- fused gather + softmax-normalize + elu, both relations ----
__device__ __forceinline__ float eluf(float v) {
    return (v > 0.f) ? v : expm1f(v);
}

__global__ void __launch_bounds__(256) gather_k(
    const int* __restrict__ p0, const int* __restrict__ c0,
    const __half* __restrict__ f0, const float* __restrict__ el0,
    const float* __restrict__ er0, const float* __restrict__ bb0,
    const int* __restrict__ p1, const int* __restrict__ c1,
    const __half* __restrict__ f1, const float* __restrict__ el1,
    const float* __restrict__ er1, const float* __restrict__ bb1,
    float* __restrict__ hout) {
    int v = (int)(((size_t)blockIdx.x * blockDim.x + threadIdx.x) >> 5);
    if (v >= Nn) return;
    int lane = threadIdx.x & 31;
    int h = lane >> 4;  // lanes 0-15: head 0 (cols 0-63), 16-31: head 1

    float ox, oy, oz, ow;
    // relation 0
    {
        int beg = v ? __ldg(&p0[v - 1]) : 0;
        int end = __ldg(&p0[v]);
        float erh = __ldg(&er0[v * NH + h]);
        float ax = 0.f, ay = 0.f, az = 0.f, aw = 0.f, s = 0.f;
        for (int e = beg; e < end; e++) {
            int u = __ldg(&c0[e]);
            float sc = __ldg(&el0[u * NH + h]) + erh;
            sc = (sc > 0.f) ? sc : 0.2f * sc;
            float w = __expf(sc);
            s += w;
            uint2 q = __ldg((const uint2*)(f0 + (size_t)u * Fd + lane * 4));
            float2 fa = __half22float2(*(__half2*)&q.x);
            float2 fb = __half22float2(*(__half2*)&q.y);
            ax += fa.x * w; ay += fa.y * w; az += fb.x * w; aw += fb.y * w;
        }
        float inv = (s > 0.f) ? 1.f / s : 0.f;
        float4 bv = *(const float4*)&bb0[lane * 4];
        ox = eluf(ax * inv + bv.x);
        oy = eluf(ay * inv + bv.y);
        oz = eluf(az * inv + bv.z);
        ow = eluf(aw * inv + bv.w);
    }
    // relation 1
    {
        int beg = v ? __ldg(&p1[v - 1]) : 0;
        int end = __ldg(&p1[v]);
        float erh = __ldg(&er1[v * NH + h]);
        float ax = 0.f, ay = 0.f, az = 0.f, aw = 0.f, s = 0.f;
        for (int e = beg; e < end; e++) {
            int u = __ldg(&c1[e]);
            float sc = __ldg(&el1[u * NH + h]) + erh;
            sc = (sc > 0.f) ? sc : 0.2f * sc;
            float w = __expf(sc);
            s += w;
            uint2 q = __ldg((const uint2*)(f1 + (size_t)u * Fd + lane * 4));
            float2 fa = __half22float2(*(__half2*)&q.x);
            float2 fb = __half22float2(*(__half2*)&q.y);
            ax += fa.x * w; ay += fa.y * w; az += fb.x * w; aw += fb.y * w;
        }
        float inv = (s > 0.f) ? 1.f / s : 0.f;
        float4 bv = *(const float4*)&bb1[lane * 4];
        ox += eluf(ax * inv + bv.x);
        oy += eluf(ay * inv + bv.y);
        oz += eluf(az * inv + bv.z);
        ow += eluf(aw * inv + bv.w);
    }
    *(float4*)&hout[(size_t)v * Fd + lane * 4] = make_float4(ox, oy, oz, ow);
}

// ---------------- drivers ----------------
static void run_layer(const float* hin, const float* W, const float* al,
                      const float* ar, const float* b,
                      const int* ptr, const int* csr, int gbase,
                      __half* f0, __half* f1,
                      float* el0, float* er0, float* el1, float* er1,
                      float* hout) {
    dim3 gg((Nn + 127) / 128, 2);
    gemm_scores_k<<<gg, 256, GEMM_SMEM>>>(hin, W, al, ar, f0, f1,
                                          el0, er0, el1, er1, Nn);
    gather_k<<<(Nn * 32 + 255) / 256, 256>>>(
        ptr + (size_t)(gbase + 0) * Nn, csr + (size_t)(gbase + 0) * Ee,
        f0, el0, er0, b,
        ptr + (size_t)(gbase + 1) * Nn, csr + (size_t)(gbase + 1) * Ee,
        f1, el1, er1, b + Fd, hout);
}

extern "C" void kernel_launch(void* const* d_in, const int* in_sizes, int n_in,
                              void* d_out, int out_size) {
    const float* x   = (const float*)d_in[0];
    const float* W0  = (const float*)d_in[1];
    const float* al0 = (const float*)d_in[2];
    const float* ar0 = (const float*)d_in[3];
    const float* b0  = (const float*)d_in[4];
    const float* W1  = (const float*)d_in[5];
    const float* al1 = (const float*)d_in[6];
    const float* ar1 = (const float*)d_in[7];
    const float* b1  = (const float*)d_in[8];
    const int* src0  = (const int*)d_in[9];
    const int* dst0  = (const int*)d_in[10];
    const int* src1  = (const int*)d_in[11];
    const int* dst1  = (const int*)d_in[12];
    float* out = (float*)d_out;

    __half *f0, *f1;
    float *h1, *el0, *er0, *el1, *er1;
    int *ptr, *csr, *part;
    cudaGetSymbolAddress((void**)&f0, g_f0);
    cudaGetSymbolAddress((void**)&f1, g_f1);
    cudaGetSymbolAddress((void**)&h1, g_h1);
    cudaGetSymbolAddress((void**)&el0, g_el0);
    cudaGetSymbolAddress((void**)&er0, g_er0);
    cudaGetSymbolAddress((void**)&el1, g_el1);
    cudaGetSymbolAddress((void**)&er1, g_er1);
    cudaGetSymbolAddress((void**)&ptr, g_ptr);
    cudaGetSymbolAddress((void**)&csr, g_csr);
    cudaGetSymbolAddress((void**)&part, g_part);

    cudaFuncSetAttribute(gemm_scores_k, cudaFuncAttributeMaxDynamicSharedMemorySize,
                         GEMM_SMEM);

    // batched CSR build: graphs {0,1} = layer0 rel0/1, {2,3} = layer1 rel0/1
    cudaMemsetAsync(ptr, 0, 4 * (size_t)Nn * sizeof(int));
    const int NE4 = (int)((4LL * Ee + 255) / 256);
    hist4_k<<<NE4, 256>>>(dst0, dst1, ptr);
    dim3 sg(NB_SCAN, 4);
    scanA_k<<<sg, 1024>>>(ptr, part);
    scanB_k<<<4, 32>>>(part);
    scanC_k<<<sg, 1024>>>(ptr, part);
    scat4_k<<<NE4, 256>>>(src0, dst0, src1, dst1, ptr, csr);

    run_layer(x, W0, al0, ar0, b0, ptr, csr, 0,
              f0, f1, el0, er0, el1, er1, h1);
    run_layer(h1, W1, al1, ar1, b1, ptr, csr, 2,
              f0, f1, el0, er0, el1, er1, out);
}

// round 10
// speedup vs baseline: 2.1215x; 1.0083x over previous
#include <cuda_runtime.h>
#include <cuda_fp16.h>
#include <cstdint>

#define Nn 50000
#define Ee 800000
#define Fd 128          // feature dim = H*OUT = 128
#define NH 2            // heads
#define NB_SCAN 49      // ceil(Nn/1024)

// ---------------- scratch (no allocations allowed) ----------------
__device__ __half g_f0[(size_t)Nn * Fd];  // projected feats (fp16), relation 0
__device__ __half g_f1[(size_t)Nn * Fd];  // projected feats (fp16), relation 1
__device__ float  g_h1[(size_t)Nn * Fd];  // layer-1 output
__device__ float  g_el0[(size_t)Nn * NH];
__device__ float  g_er0[(size_t)Nn * NH];
__device__ float  g_el1[(size_t)Nn * NH];
__device__ float  g_er1[(size_t)Nn * NH];
__device__ int    g_ptr[4][Nn];           // per-graph rowptr
__device__ int    g_csr[4][Ee];           // per-graph src ids grouped by dst
__device__ int    g_part[4 * 64];         // scan block partials

// ---------------- packed f32x2 helpers (Blackwell FFMA2 path) ----------------
__device__ __forceinline__ unsigned long long pack2(float lo, float hi) {
    unsigned long long r;
    asm("mov.b64 %0, {%1, %2};" : "=l"(r) : "f"(lo), "f"(hi));
    return r;
}
__device__ __forceinline__ void fma2(unsigned long long& d, unsigned long long a,
                                     unsigned long long b) {
    asm("fma.rn.f32x2 %0, %1, %2, %0;" : "+l"(d) : "l"(a), "l"(b));
}
__device__ __forceinline__ float2 unpack2(unsigned long long v) {
    float2 r;
    asm("mov.b64 {%0, %1}, %2;" : "=f"(r.x), "=f"(r.y) : "l"(v));
    return r;
}

// ---------------- GEMM + fused scores: both relations in one launch ----------
// C[nrows,128] = A[nrows,128] @ W[r], stored fp16; el/er computed from fp32
// accumulators via width-16 shfl reductions. blockIdx.y = relation.
#define GEMM_SMEM (128 * 132 * 4 + 128 * 128 * 4)

__global__ void __launch_bounds__(256) gemm_scores_k(
    const float* __restrict__ A, const float* __restrict__ W,
    const float* __restrict__ al, const float* __restrict__ ar,
    __half* __restrict__ fo0, __half* __restrict__ fo1,
    float* __restrict__ el0, float* __restrict__ er0,
    float* __restrict__ el1, float* __restrict__ er1, int nrows) {
    extern __shared__ float sm[];
    float* As = sm;               // [128][132] padded
    float* Bs = sm + 128 * 132;   // [128][128]
    const int r = blockIdx.y;
    const float* B = W + (size_t)r * Fd * Fd;
    __half* fout = r ? fo1 : fo0;
    float* el = r ? el1 : el0;
    float* er = r ? er1 : er0;
    const float* alr = al + r * Fd;
    const float* arr = ar + r * Fd;
    const int m0 = blockIdx.x * 128;
    const int tid = threadIdx.x;

#pragma unroll
    for (int it = 0; it < 16; it++) {
        int idx = tid + it * 256;       // float4 index, 0..4095
        int row = idx >> 5;
        int c4 = (idx & 31) << 2;
        float4 va = make_float4(0.f, 0.f, 0.f, 0.f);
        if (m0 + row < nrows) va = *(const float4*)&A[(size_t)(m0 + row) * Fd + c4];
        *(float4*)&As[row * 132 + c4] = va;
        *(float4*)&Bs[row * 128 + c4] = *(const float4*)&B[row * Fd + c4];
    }
    __syncthreads();

    const int ty = tid >> 4;   // rows ty*8..ty*8+7
    const int tx = tid & 15;   // cols tx*4 (head0) and 64+tx*4 (head1)

    unsigned long long acc[8][4];
#pragma unroll
    for (int i = 0; i < 8; i++)
#pragma unroll
        for (int j = 0; j < 4; j++) acc[i][j] = 0ull;

#pragma unroll 4
    for (int k = 0; k < 128; k++) {
        float4 b0 = *(const float4*)&Bs[k * 128 + tx * 4];
        float4 b1 = *(const float4*)&Bs[k * 128 + 64 + tx * 4];
        unsigned long long bp0 = pack2(b0.x, b0.y);
        unsigned long long bp1 = pack2(b0.z, b0.w);
        unsigned long long bp2 = pack2(b1.x, b1.y);
        unsigned long long bp3 = pack2(b1.z, b1.w);
#pragma unroll
        for (int i = 0; i < 8; i++) {
            float a = As[(ty * 8 + i) * 132 + k];
            unsigned long long ap = pack2(a, a);
            fma2(acc[i][0], ap, bp0);
            fma2(acc[i][1], ap, bp1);
            fma2(acc[i][2], ap, bp2);
            fma2(acc[i][3], ap, bp3);
        }
    }

    float4 alv0 = __ldg((const float4*)&alr[tx * 4]);
    float4 alv1 = __ldg((const float4*)&alr[64 + tx * 4]);
    float4 arv0 = __ldg((const float4*)&arr[tx * 4]);
    float4 arv1 = __ldg((const float4*)&arr[64 + tx * 4]);

#pragma unroll
    for (int i = 0; i < 8; i++) {
        int row = m0 + ty * 8 + i;
        float2 v0 = unpack2(acc[i][0]);
        float2 v1 = unpack2(acc[i][1]);
        float2 v2 = unpack2(acc[i][2]);
        float2 v3 = unpack2(acc[i][3]);
        // scores partials (per head), fp32-exact
        float pel0 = v0.x * alv0.x + v0.y * alv0.y + v1.x * alv0.z + v1.y * alv0.w;
        float pel1 = v2.x * alv1.x + v2.y * alv1.y + v3.x * alv1.z + v3.y * alv1.w;
        float per0 = v0.x * arv0.x + v0.y * arv0.y + v1.x * arv0.z + v1.y * arv0.w;
        float per1 = v2.x * arv1.x + v2.y * arv1.y + v3.x * arv1.z + v3.y * arv1.w;
#pragma unroll
        for (int off = 8; off; off >>= 1) {
            pel0 += __shfl_down_sync(0xffffffffu, pel0, off, 16);
            pel1 += __shfl_down_sync(0xffffffffu, pel1, off, 16);
            per0 += __shfl_down_sync(0xffffffffu, per0, off, 16);
            per1 += __shfl_down_sync(0xffffffffu, per1, off, 16);
        }
        if (row < nrows) {
            __half2 ha = __floats2half2_rn(v0.x, v0.y);
            __half2 hb = __floats2half2_rn(v1.x, v1.y);
            __half2 hc = __floats2half2_rn(v2.x, v2.y);
            __half2 hd = __floats2half2_rn(v3.x, v3.y);
            uint2 s0, s1;
            s0.x = *(unsigned int*)&ha; s0.y = *(unsigned int*)&hb;
            s1.x = *(unsigned int*)&hc; s1.y = *(unsigned int*)&hd;
            *(uint2*)&fout[(size_t)row * Fd + tx * 4] = s0;
            *(uint2*)&fout[(size_t)row * Fd + 64 + tx * 4] = s1;
            if (tx == 0) {
                el[row * NH + 0] = pel0;
                el[row * NH + 1] = pel1;
                er[row * NH + 0] = per0;
                er[row * NH + 1] = per1;
            }
        }
    }
}

// ---------------- batched CSR build (4 graphs in one pass each) --------------
__global__ void __launch_bounds__(256) hist4_k(const int* __restrict__ dA,
                                               const int* __restrict__ dB,
                                               int* __restrict__ cnt) {
    long long e = (long long)blockIdx.x * blockDim.x + threadIdx.x;
    if (e >= 4LL * Ee) return;
    int g = (int)(e / Ee);
    int i = (int)(e - (long long)g * Ee);
    const int* d = (g < 2) ? (dA + (size_t)g * Ee) : (dB + (size_t)(g - 2) * Ee);
    atomicAdd(&cnt[g * Nn + d[i]], 1);
}

__global__ void __launch_bounds__(1024) scanA_k(int* __restrict__ cnt,
                                                int* __restrict__ part) {
    __shared__ int sm[1024];
    int g = blockIdx.y;
    int i = blockIdx.x * 1024 + threadIdx.x;
    int v = (i < Nn) ? cnt[g * Nn + i] : 0;
    sm[threadIdx.x] = v;
    __syncthreads();
#pragma unroll
    for (int off = 1; off < 1024; off <<= 1) {
        int t = (threadIdx.x >= off) ? sm[threadIdx.x - off] : 0;
        __syncthreads();
        sm[threadIdx.x] += t;
        __syncthreads();
    }
    int incl = sm[threadIdx.x];
    if (i < Nn) cnt[g * Nn + i] = incl - v;        // exclusive within block
    if (threadIdx.x == 1023) part[g * 64 + blockIdx.x] = incl;
}

__global__ void scanB_k(int* __restrict__ part) {
    if (threadIdx.x == 0) {
        int* p = part + blockIdx.x * 64;
        int acc = 0;
        for (int i = 0; i < NB_SCAN; i++) { int t = p[i]; p[i] = acc; acc += t; }
    }
}

__global__ void __launch_bounds__(1024) scanC_k(int* __restrict__ cnt,
                                                const int* __restrict__ part) {
    int g = blockIdx.y;
    int i = blockIdx.x * 1024 + threadIdx.x;
    if (i < Nn) cnt[g * Nn + i] += part[g * 64 + blockIdx.x];
}

// scatter: ptr[v] holds exclusive start; atomic bump -> inclusive end.
__global__ void __launch_bounds__(256) scat4_k(const int* __restrict__ sA,
                                               const int* __restrict__ dA,
                                               const int* __restrict__ sB,
                                               const int* __restrict__ dB,
                                               int* __restrict__ ptr,
                                               int* __restrict__ csr) {
    long long e = (long long)blockIdx.x * blockDim.x + threadIdx.x;
    if (e >= 4LL * Ee) return;
    int g = (int)(e / Ee);
    int i = (int)(e - (long long)g * Ee);
    const int* s = (g < 2) ? (sA + (size_t)g * Ee) : (sB + (size_t)(g - 2) * Ee);
    const int* d = (g < 2) ? (dA + (size_t)g * Ee) : (dB + (size_t)(g - 2) * Ee);
    int v = d[i];
    int pos = atomicAdd(&ptr[g * Nn + v], 1);
    csr[(size_t)g * Ee + pos] = s[i];
}

// ---------------- fused gather + softmax-normalize + elu, both relations ----
__device__ __forceinline__ float eluf(float v) {
    return (v > 0.f) ? v : expm1f(v);
}

__global__ void __launch_bounds__(256) gather_k(
    const int* __restrict__ p0, const int* __restrict__ c0,
    const __half* __restrict__ f0, const float* __restrict__ el0,
    const float* __restrict__ er0, const float* __restrict__ bb0,
    const int* __restrict__ p1, const int* __restrict__ c1,
    const __half* __restrict__ f1, const float* __restrict__ el1,
    const float* __restrict__ er1, const float* __restrict__ bb1,
    float* __restrict__ hout) {
    int v = (int)(((size_t)blockIdx.x * blockDim.x + threadIdx.x) >> 5);
    if (v >= Nn) return;
    int lane = threadIdx.x & 31;
    int h = lane >> 4;  // lanes 0-15: head 0 (cols 0-63), 16-31: head 1

    float ox, oy, oz, ow;
    // relation 0
    {
        int beg = v ? __ldg(&p0[v - 1]) : 0;
        int end = __ldg(&p0[v]);
        float erh = __ldg(&er0[v * NH + h]);
        float ax = 0.f, ay = 0.f, az = 0.f, aw = 0.f, s = 0.f;
        for (int e = beg; e < end; e++) {
            int u = __ldg(&c0[e]);
            float sc = __ldg(&el0[u * NH + h]) + erh;
            sc = (sc > 0.f) ? sc : 0.2f * sc;
            float w = __expf(sc);
            s += w;
            uint2 q = __ldg((const uint2*)(f0 + (size_t)u * Fd + lane * 4));
            float2 fa = __half22float2(*(__half2*)&q.x);
            float2 fb = __half22float2(*(__half2*)&q.y);
            ax += fa.x * w; ay += fa.y * w; az += fb.x * w; aw += fb.y * w;
        }
        float inv = (s > 0.f) ? 1.f / s : 0.f;
        float4 bv = *(const float4*)&bb0[lane * 4];
        ox = eluf(ax * inv + bv.x);
        oy = eluf(ay * inv + bv.y);
        oz = eluf(az * inv + bv.z);
        ow = eluf(aw * inv + bv.w);
    }
    // relation 1
    {
        int beg = v ? __ldg(&p1[v - 1]) : 0;
        int end = __ldg(&p1[v]);
        float erh = __ldg(&er1[v * NH + h]);
        float ax = 0.f, ay = 0.f, az = 0.f, aw = 0.f, s = 0.f;
        for (int e = beg; e < end; e++) {
            int u = __ldg(&c1[e]);
            float sc = __ldg(&el1[u * NH + h]) + erh;
            sc = (sc > 0.f) ? sc : 0.2f * sc;
            float w = __expf(sc);
            s += w;
            uint2 q = __ldg((const uint2*)(f1 + (size_t)u * Fd + lane * 4));
            float2 fa = __half22float2(*(__half2*)&q.x);
            float2 fb = __half22float2(*(__half2*)&q.y);
            ax += fa.x * w; ay += fa.y * w; az += fb.x * w; aw += fb.y * w;
        }
        float inv = (s > 0.f) ? 1.f / s : 0.f;
        float4 bv = *(const float4*)&bb1[lane * 4];
        ox += eluf(ax * inv + bv.x);
        oy += eluf(ay * inv + bv.y);
        oz += eluf(az * inv + bv.z);
        ow += eluf(aw * inv + bv.w);
    }
    *(float4*)&hout[(size_t)v * Fd + lane * 4] = make_float4(ox, oy, oz, ow);
}

// ---------------- drivers ----------------
static void run_layer(const float* hin, const float* W, const float* al,
                      const float* ar, const float* b,
                      const int* ptr, const int* csr, int gbase,
                      __half* f0, __half* f1,
                      float* el0, float* er0, float* el1, float* er1,
                      float* hout) {
    dim3 gg((Nn + 127) / 128, 2);
    gemm_scores_k<<<gg, 256, GEMM_SMEM>>>(hin, W, al, ar, f0, f1,
                                          el0, er0, el1, er1, Nn);
    gather_k<<<(Nn * 32 + 255) / 256, 256>>>(
        ptr + (size_t)(gbase + 0) * Nn, csr + (size_t)(gbase + 0) * Ee,
        f0, el0, er0, b,
        ptr + (size_t)(gbase + 1) * Nn, csr + (size_t)(gbase + 1) * Ee,
        f1, el1, er1, b + Fd, hout);
}

extern "C" void kernel_launch(void* const* d_in, const int* in_sizes, int n_in,
                              void* d_out, int out_size) {
    const float* x   = (const float*)d_in[0];
    const float* W0  = (const float*)d_in[1];
    const float* al0 = (const float*)d_in[2];
    const float* ar0 = (const float*)d_in[3];
    const float* b0  = (const float*)d_in[4];
    const float* W1  = (const float*)d_in[5];
    const float* al1 = (const float*)d_in[6];
    const float* ar1 = (const float*)d_in[7];
    const float* b1  = (const float*)d_in[8];
    const int* src0  = (const int*)d_in[9];
    const int* dst0  = (const int*)d_in[10];
    const int* src1  = (const int*)d_in[11];
    const int* dst1  = (const int*)d_in[12];
    float* out = (float*)d_out;

    __half *f0, *f1;
    float *h1, *el0, *er0, *el1, *er1;
    int *ptr, *csr, *part;
    cudaGetSymbolAddress((void**)&f0, g_f0);
    cudaGetSymbolAddress((void**)&f1, g_f1);
    cudaGetSymbolAddress((void**)&h1, g_h1);
    cudaGetSymbolAddress((void**)&el0, g_el0);
    cudaGetSymbolAddress((void**)&er0, g_er0);
    cudaGetSymbolAddress((void**)&el1, g_el1);
    cudaGetSymbolAddress((void**)&er1, g_er1);
    cudaGetSymbolAddress((void**)&ptr, g_ptr);
    cudaGetSymbolAddress((void**)&csr, g_csr);
    cudaGetSymbolAddress((void**)&part, g_part);

    cudaFuncSetAttribute(gemm_scores_k, cudaFuncAttributeMaxDynamicSharedMemorySize,
                         GEMM_SMEM);

    // batched CSR build: graphs {0,1} = layer0 rel0/1, {2,3} = layer1 rel0/1
    cudaMemsetAsync(ptr, 0, 4 * (size_t)Nn * sizeof(int));
    const int NE4 = (int)((4LL * Ee + 255) / 256);
    hist4_k<<<NE4, 256>>>(dst0, dst1, ptr);
    dim3 sg(NB_SCAN, 4);
    scanA_k<<<sg, 1024>>>(ptr, part);
    scanB_k<<<4, 32>>>(part);
    scanC_k<<<sg, 1024>>>(ptr, part);
    scat4_k<<<NE4, 256>>>(src0, dst0, src1, dst1, ptr, csr);

    run_layer(x, W0, al0, ar0, b0, ptr, csr, 0,
              f0, f1, el0, er0, el1, er1, h1);
    run_layer(h1, W1, al1, ar1, b1, ptr, csr, 2,
              f0, f1, el0, er0, el1, er1, out);
}